// round 5
// baseline (speedup 1.0000x reference)
#include <cuda_runtime.h>

// ContrastiveTreeLoss: margin loss between gold tree score and K negative tree
// scores derived from per-dependent arc gathers.
//
// Shapes (fixed by the problem instance):
//   arc_scores [B=512, N=256, N=256] f32
//   gold_heads [B, N] i32
//   mask       [B, N] i32
//   neg_heads  [K=4, B, N] i32
//   out        scalar f32 = mean_{k,b} relu(MARGIN - gold_total[b] + neg_total[k,b])

#define TL_B 512
#define TL_N 256
#define TL_K 4
#define TL_MARGIN 2.0f

// Per-sentence partial losses (sum over k of relu terms). Scratch via device
// global — no allocation allowed in kernel_launch.
__device__ float g_partial[TL_B];

__global__ __launch_bounds__(TL_N, 4)
void tree_loss_kernel(const float* __restrict__ arc,
                      const int*   __restrict__ gold,
                      const int*   __restrict__ mask,
                      const int*   __restrict__ neg)
{
    const int b = blockIdx.x;     // sentence
    const int d = threadIdx.x;    // dependent index 0..N-1 (d=0 unused)
    const float* __restrict__ arcb = arc + (size_t)b * TL_N * TL_N;

    float vals[TL_K + 1];
#pragma unroll
    for (int i = 0; i < TL_K + 1; i++) vals[i] = 0.0f;

    if (d >= 1) {
        const float m = (float)__ldg(&mask[b * TL_N + d]);
        int gh = __ldg(&gold[b * TL_N + d]);
        gh = min(max(gh, 0), TL_N - 1);
        // Gold gather: arc[b, gh, d]
        vals[0] = __ldg(arcb + gh * TL_N + d) * m;
        // Negative gathers (mostly same address as gold -> L1 hits after miss)
#pragma unroll
        for (int k = 0; k < TL_K; k++) {
            int nh = __ldg(&neg[((size_t)k * TL_B + b) * TL_N + d]);
            nh = min(max(nh, 0), TL_N - 1);
            vals[1 + k] = __ldg(arcb + nh * TL_N + d) * m;
        }
    }

    // 5-way block reduction: warp shuffle -> 8 warp-partials in smem -> warp 0
    __shared__ float sh[8][TL_K + 1];
    const int lane = d & 31;
    const int warp = d >> 5;
#pragma unroll
    for (int i = 0; i < TL_K + 1; i++) {
        float v = vals[i];
#pragma unroll
        for (int off = 16; off > 0; off >>= 1)
            v += __shfl_down_sync(0xffffffffu, v, off);
        if (lane == 0) sh[warp][i] = v;
    }
    __syncthreads();

    if (d < 32) {
#pragma unroll
        for (int i = 0; i < TL_K + 1; i++) {
            float v = (d < 8) ? sh[d][i] : 0.0f;
#pragma unroll
            for (int off = 4; off > 0; off >>= 1)
                v += __shfl_down_sync(0xffffffffu, v, off);
            vals[i] = v;   // lane 0 holds the total
        }
        if (d == 0) {
            const float gold_total = vals[0];
            float loss = 0.0f;
#pragma unroll
            for (int k = 0; k < TL_K; k++)
                loss += fmaxf(TL_MARGIN - gold_total + vals[1 + k], 0.0f);
            g_partial[b] = loss;
        }
    }
}

__global__ __launch_bounds__(TL_B)
void tree_loss_reduce_kernel(float* __restrict__ out)
{
    const int t = threadIdx.x;          // 512 threads = 16 warps
    float v = g_partial[t];
    __shared__ float sh[16];
#pragma unroll
    for (int off = 16; off > 0; off >>= 1)
        v += __shfl_down_sync(0xffffffffu, v, off);
    if ((t & 31) == 0) sh[t >> 5] = v;
    __syncthreads();
    if (t < 32) {
        float w = (t < 16) ? sh[t] : 0.0f;
#pragma unroll
        for (int off = 8; off > 0; off >>= 1)
            w += __shfl_down_sync(0xffffffffu, w, off);
        if (t == 0) out[0] = w * (1.0f / (float)(TL_K * TL_B));
    }
}

extern "C" void kernel_launch(void* const* d_in, const int* in_sizes, int n_in,
                              void* d_out, int out_size)
{
    const float* arc  = (const float*)d_in[0];  // arc_scores [B,N,N]
    const int*   gold = (const int*)  d_in[1];  // gold_heads [B,N]
    const int*   mask = (const int*)  d_in[2];  // mask       [B,N]
    const int*   neg  = (const int*)  d_in[3];  // neg_heads  [K,B,N]
    (void)in_sizes; (void)n_in; (void)out_size;

    tree_loss_kernel<<<TL_B, TL_N>>>(arc, gold, mask, neg);
    tree_loss_reduce_kernel<<<1, TL_B>>>((float*)d_out);
}